// round 2
// baseline (speedup 1.0000x reference)
#include <cuda_runtime.h>
#include <cuda_bf16.h>
#include <math.h>

#define L_   2048
#define NB_  4
#define E_   512
#define H_   8
#define D_   64
#define EPS_ 1e-6f

// ---------------- scratch (static __device__, no allocations) ----------------
__device__ float g_q[(size_t)NB_ * H_ * L_ * D_];        // 16 MB
__device__ float g_k[(size_t)NB_ * H_ * L_ * D_];        // 16 MB
__device__ float g_vp[(size_t)NB_ * H_ * L_ * D_];       // 16 MB (= max(v+shift,eps)^p)
__device__ float g_scores[(size_t)NB_ * H_ * L_ * L_];   // 512 MB
__device__ float g_oh[(size_t)L_ * NB_ * E_];            // 16 MB (GeM-inverted heads, (L*N, E))

// MODE: 0 = Q proj, 1 = K proj, 2 = V proj (+GeM fwd pow), 3 = scores QK^T, 4 = out proj
// Computes C[m][j] = sum_k A[m][k] * B[j][k]  (TN GEMM, both row-major)
// Double-buffered smem mainloop: one __syncthreads per K-tile.
template <int MODE>
__global__ void __launch_bounds__(256)
sgemm_tn(const float* __restrict__ A, const float* __restrict__ B,
         const float* __restrict__ bias, float* __restrict__ C,
         int M, int N, int K, int lda, int ldb,
         const float* __restrict__ pvec, const float* __restrict__ shvec)
{
    __shared__ float As[2][8][128];
    __shared__ float Bs[2][8][128];

    const int bx = blockIdx.x, by = blockIdx.y, bz = blockIdx.z;

    const float* Aptr = (MODE == 3) ? (const float*)g_q + (size_t)bz * L_ * D_
                       : (MODE == 4) ? (const float*)g_oh
                       : A;
    const float* Bptr = (MODE == 3) ? (const float*)g_k + (size_t)bz * L_ * D_ : B;

    const int m0 = by * 128, n0 = bx * 128;
    const int t  = threadIdx.x;
    const int tx = t & 15, ty = t >> 4;
    const int lrow = t >> 1;
    const int lcol = (t & 1) * 4;

    const float* Aload = Aptr + (size_t)(m0 + lrow) * lda + lcol;
    const float* Bload = Bptr + (size_t)(n0 + lrow) * ldb + lcol;

    float acc[8][8];
#pragma unroll
    for (int i = 0; i < 8; i++)
#pragma unroll
        for (int j = 0; j < 8; j++) acc[i][j] = 0.f;

    const int T = K >> 3;   // number of 8-wide K tiles

    // prologue: tile 0 -> buffer 0
    {
        float4 av = *(const float4*)(Aload);
        float4 bv = *(const float4*)(Bload);
        As[0][lcol + 0][lrow] = av.x; As[0][lcol + 1][lrow] = av.y;
        As[0][lcol + 2][lrow] = av.z; As[0][lcol + 3][lrow] = av.w;
        Bs[0][lcol + 0][lrow] = bv.x; Bs[0][lcol + 1][lrow] = bv.y;
        Bs[0][lcol + 2][lrow] = bv.z; Bs[0][lcol + 3][lrow] = bv.w;
    }
    __syncthreads();

    int cur = 0;
    for (int it = 0; it < T; ++it) {
        float4 av2, bv2;
        const bool more = (it + 1 < T);
        if (more) {
            av2 = *(const float4*)(Aload + (it + 1) * 8);
            bv2 = *(const float4*)(Bload + (it + 1) * 8);
        }
#pragma unroll
        for (int kk = 0; kk < 8; kk++) {
            float a[8], b[8];
            *(float4*)&a[0] = *(const float4*)&As[cur][kk][ty * 8];
            *(float4*)&a[4] = *(const float4*)&As[cur][kk][ty * 8 + 4];
            *(float4*)&b[0] = *(const float4*)&Bs[cur][kk][tx * 8];
            *(float4*)&b[4] = *(const float4*)&Bs[cur][kk][tx * 8 + 4];
#pragma unroll
            for (int i = 0; i < 8; i++)
#pragma unroll
                for (int j = 0; j < 8; j++)
                    acc[i][j] = fmaf(a[i], b[j], acc[i][j]);
        }
        if (more) {
            const int nxt = cur ^ 1;
            As[nxt][lcol + 0][lrow] = av2.x; As[nxt][lcol + 1][lrow] = av2.y;
            As[nxt][lcol + 2][lrow] = av2.z; As[nxt][lcol + 3][lrow] = av2.w;
            Bs[nxt][lcol + 0][lrow] = bv2.x; Bs[nxt][lcol + 1][lrow] = bv2.y;
            Bs[nxt][lcol + 2][lrow] = bv2.z; Bs[nxt][lcol + 3][lrow] = bv2.w;
            __syncthreads();
            cur = nxt;
        }
    }

    // ---------------- epilogues ----------------
    if (MODE <= 2) {
        const int ebase = n0 + tx * 8;      // output feature e, 8-aligned -> single head
        const int h  = ebase >> 6;
        const int d0 = ebase & 63;
        float bb[8], pp[8], ss[8];
#pragma unroll
        for (int j = 0; j < 8; j++) bb[j] = bias[ebase + j];
        if (MODE == 2) {
#pragma unroll
            for (int j = 0; j < 8; j++) { pp[j] = pvec[ebase + j]; ss[j] = shvec[ebase + j]; }
        }
        float* dst = (MODE == 0) ? g_q : (MODE == 1) ? g_k : g_vp;
#pragma unroll
        for (int i = 0; i < 8; i++) {
            int m = m0 + ty * 8 + i;
            int l = m >> 2, n = m & 3;
            float* base = dst + (((size_t)(n * H_ + h) * L_ + l) * D_ + d0);
            float v[8];
#pragma unroll
            for (int j = 0; j < 8; j++) {
                float x = acc[i][j] + bb[j];
                if (MODE == 2) x = __powf(fmaxf(x + ss[j], EPS_), pp[j]);
                v[j] = x;
            }
            *(float4*)(base)     = make_float4(v[0], v[1], v[2], v[3]);
            *(float4*)(base + 4) = make_float4(v[4], v[5], v[6], v[7]);
        }
    } else if (MODE == 3) {
        const float scale = 0.125f;   // 1/sqrt(64)
        float* dst = g_scores + (size_t)bz * L_ * L_;
#pragma unroll
        for (int i = 0; i < 8; i++) {
            int m = m0 + ty * 8 + i;
            float* base = dst + (size_t)m * L_ + n0 + tx * 8;
            *(float4*)(base)     = make_float4(acc[i][0] * scale, acc[i][1] * scale,
                                               acc[i][2] * scale, acc[i][3] * scale);
            *(float4*)(base + 4) = make_float4(acc[i][4] * scale, acc[i][5] * scale,
                                               acc[i][6] * scale, acc[i][7] * scale);
        }
    } else {
        const int ebase = n0 + tx * 8;
        float bb[8];
#pragma unroll
        for (int j = 0; j < 8; j++) bb[j] = bias[ebase + j];
#pragma unroll
        for (int i = 0; i < 8; i++) {
            int m = m0 + ty * 8 + i;
            float* base = C + (size_t)m * E_ + ebase;
            *(float4*)(base)     = make_float4(acc[i][0] + bb[0], acc[i][1] + bb[1],
                                               acc[i][2] + bb[2], acc[i][3] + bb[3]);
            *(float4*)(base + 4) = make_float4(acc[i][4] + bb[4], acc[i][5] + bb[5],
                                               acc[i][6] + bb[6], acc[i][7] + bb[7]);
        }
    }
}

// Row softmax (in-place, normalized), one block per row of 2048
__global__ void __launch_bounds__(256) softmax_kernel()
{
    float* row = g_scores + (size_t)blockIdx.x * L_;
    const int t = threadIdx.x;
    float4* rv = (float4*)row;
    float4 a = rv[t];
    float4 b = rv[t + 256];

    __shared__ float red[8];

    float m = fmaxf(fmaxf(fmaxf(a.x, a.y), fmaxf(a.z, a.w)),
                    fmaxf(fmaxf(b.x, b.y), fmaxf(b.z, b.w)));
#pragma unroll
    for (int o = 16; o > 0; o >>= 1) m = fmaxf(m, __shfl_xor_sync(0xffffffffu, m, o));
    if ((t & 31) == 0) red[t >> 5] = m;
    __syncthreads();
    float mAll = red[0];
#pragma unroll
    for (int w = 1; w < 8; w++) mAll = fmaxf(mAll, red[w]);

    a.x = __expf(a.x - mAll); a.y = __expf(a.y - mAll);
    a.z = __expf(a.z - mAll); a.w = __expf(a.w - mAll);
    b.x = __expf(b.x - mAll); b.y = __expf(b.y - mAll);
    b.z = __expf(b.z - mAll); b.w = __expf(b.w - mAll);

    float s = a.x + a.y + a.z + a.w + b.x + b.y + b.z + b.w;
    __syncthreads();     // red reuse
#pragma unroll
    for (int o = 16; o > 0; o >>= 1) s += __shfl_xor_sync(0xffffffffu, s, o);
    if ((t & 31) == 0) red[t >> 5] = s;
    __syncthreads();
    float sAll = red[0];
#pragma unroll
    for (int w = 1; w < 8; w++) sAll += red[w];

    float inv = 1.0f / sAll;
    a.x *= inv; a.y *= inv; a.z *= inv; a.w *= inv;
    b.x *= inv; b.y *= inv; b.z *= inv; b.w *= inv;
    rv[t] = a; rv[t + 256] = b;
}

// pooled = attn(2048x2048) @ vp(2048x64), NN GEMM; epilogue: GeM inverse -> g_oh
// Double-buffered smem mainloop.
__global__ void __launch_bounds__(256)
pool_gemm(const float* __restrict__ pvec, const float* __restrict__ shvec)
{
    __shared__ float As[2][8][128];
    __shared__ float Bs[2][8][64];

    const int by = blockIdx.x;   // m tile 0..15
    const int bz = blockIdx.y;   // batch 0..31 (n*8+h)
    const int m0 = by * 128;
    const float* A = g_scores + (size_t)bz * L_ * L_;
    const float* B = g_vp + (size_t)bz * L_ * D_;

    const int t  = threadIdx.x;
    const int tx = t & 15, ty = t >> 4;
    const int lrow = t >> 1, lcol = (t & 1) * 4;
    const bool bload = (t < 128);
    const int kr = t >> 4;            // 0..7 when t < 128
    const int jc = (t & 15) * 4;

    float acc[8][4];
#pragma unroll
    for (int i = 0; i < 8; i++)
#pragma unroll
        for (int j = 0; j < 4; j++) acc[i][j] = 0.f;

    const int T = L_ >> 3;   // 256 tiles

    // prologue: tile 0 -> buffer 0
    {
        float4 av = *(const float4*)(A + (size_t)(m0 + lrow) * L_ + lcol);
        As[0][lcol + 0][lrow] = av.x; As[0][lcol + 1][lrow] = av.y;
        As[0][lcol + 2][lrow] = av.z; As[0][lcol + 3][lrow] = av.w;
        if (bload) {
            float4 bv = *(const float4*)(B + (size_t)kr * D_ + jc);
            Bs[0][kr][jc + 0] = bv.x; Bs[0][kr][jc + 1] = bv.y;
            Bs[0][kr][jc + 2] = bv.z; Bs[0][kr][jc + 3] = bv.w;
        }
    }
    __syncthreads();

    int cur = 0;
    for (int it = 0; it < T; ++it) {
        float4 av2, bv2;
        const bool more = (it + 1 < T);
        const int k0n = (it + 1) * 8;
        if (more) {
            av2 = *(const float4*)(A + (size_t)(m0 + lrow) * L_ + k0n + lcol);
            if (bload) bv2 = *(const float4*)(B + (size_t)(k0n + kr) * D_ + jc);
        }
#pragma unroll
        for (int kk = 0; kk < 8; kk++) {
            float a[8], b[4];
            *(float4*)&a[0] = *(const float4*)&As[cur][kk][ty * 8];
            *(float4*)&a[4] = *(const float4*)&As[cur][kk][ty * 8 + 4];
            *(float4*)&b[0] = *(const float4*)&Bs[cur][kk][tx * 4];
#pragma unroll
            for (int i = 0; i < 8; i++)
#pragma unroll
                for (int j = 0; j < 4; j++)
                    acc[i][j] = fmaf(a[i], b[j], acc[i][j]);
        }
        if (more) {
            const int nxt = cur ^ 1;
            As[nxt][lcol + 0][lrow] = av2.x; As[nxt][lcol + 1][lrow] = av2.y;
            As[nxt][lcol + 2][lrow] = av2.z; As[nxt][lcol + 3][lrow] = av2.w;
            if (bload) {
                Bs[nxt][kr][jc + 0] = bv2.x; Bs[nxt][kr][jc + 1] = bv2.y;
                Bs[nxt][kr][jc + 2] = bv2.z; Bs[nxt][kr][jc + 3] = bv2.w;
            }
            __syncthreads();
            cur = nxt;
        }
    }

    // GeM inverse epilogue
    const int n = bz >> 3, h = bz & 7;
    const int d0 = tx * 4;
    const int e0 = h * 64 + d0;
    float rp[4], ss[4];
#pragma unroll
    for (int j = 0; j < 4; j++) { rp[j] = 1.0f / pvec[e0 + j]; ss[j] = shvec[e0 + j]; }
#pragma unroll
    for (int i = 0; i < 8; i++) {
        int l = m0 + ty * 8 + i;
        float v[4];
#pragma unroll
        for (int j = 0; j < 4; j++)
            v[j] = __powf(fmaxf(acc[i][j], EPS_), rp[j]) - ss[j];
        *(float4*)&g_oh[((size_t)l * NB_ + n) * E_ + e0] = make_float4(v[0], v[1], v[2], v[3]);
    }
}

extern "C" void kernel_launch(void* const* d_in, const int* in_sizes, int n_in,
                              void* d_out, int out_size)
{
    const float* query = (const float*)d_in[0];
    const float* key_  = (const float*)d_in[1];
    const float* value = (const float*)d_in[2];
    const float* wIn   = (const float*)d_in[3];   // (1536, 512)
    const float* bIn   = (const float*)d_in[4];   // (1536,)
    const float* wOut  = (const float*)d_in[5];   // (512, 512)
    const float* bOut  = (const float*)d_in[6];   // (512,)
    const float* p     = (const float*)d_in[7];   // (512,)
    const float* shift = (const float*)d_in[8];   // (512,)
    float* out = (float*)d_out;

    dim3 blk(256);

    // in-projections: (8192x512) @ (512x512)^T
    sgemm_tn<0><<<dim3(4, 64), blk>>>(query, wIn,              bIn,        nullptr,
                                      8192, 512, 512, 512, 512, nullptr, nullptr);
    sgemm_tn<1><<<dim3(4, 64), blk>>>(key_,  wIn + 512 * 512,  bIn + 512,  nullptr,
                                      8192, 512, 512, 512, 512, nullptr, nullptr);
    sgemm_tn<2><<<dim3(4, 64), blk>>>(value, wIn + 1024 * 512, bIn + 1024, nullptr,
                                      8192, 512, 512, 512, 512, p, shift);

    // scores = q @ k^T * scale, batched over 32 (n,h)
    sgemm_tn<3><<<dim3(16, 16, 32), blk>>>(nullptr, nullptr, nullptr, nullptr,
                                           2048, 2048, 64, 64, 64, nullptr, nullptr);

    // softmax rows (in-place)
    softmax_kernel<<<32 * 2048, 256>>>();

    // pooled = attn @ vp, GeM-inverse epilogue -> g_oh
    pool_gemm<<<dim3(16, 32), blk>>>(p, shift);

    // out = oh @ wOut^T + bOut
    sgemm_tn<4><<<dim3(4, 64), blk>>>(nullptr, wOut, bOut, out,
                                      8192, 512, 512, 512, 512, nullptr, nullptr);
}